// round 12
// baseline (speedup 1.0000x reference)
#include <cuda_runtime.h>
#include <cstdint>

#define N_PRE    50000
#define VEC_DIM  300        // 75 float4
#define HIDDEN   128        // 32 float4
#define IN_SIZE  50000
#define OUT_DIM  428        // 107 float4
#define N_TOKENS (64 * 200)

// Cache-policy register: L2 evict_last for the persistent read set (W, vectors).
static __device__ __forceinline__ uint64_t mk_policy_evict_last() {
    uint64_t pol;
    asm volatile("createpolicy.fractional.L2::evict_last.b64 %0, 1.0;"
                 : "=l"(pol));
    return pol;
}
static __device__ __forceinline__ float ldg_el_f32(const float* p, uint64_t pol) {
    float v;
    asm volatile("ld.global.nc.L2::cache_hint.f32 %0, [%1], %2;"
                 : "=f"(v) : "l"(p), "l"(pol));
    return v;
}
static __device__ __forceinline__ float4 ldg_el_f128(const float4* p, uint64_t pol) {
    float4 v;
    asm volatile("ld.global.nc.L2::cache_hint.v4.f32 {%0,%1,%2,%3}, [%4], %5;"
                 : "=f"(v.x), "=f"(v.y), "=f"(v.z), "=f"(v.w)
                 : "l"(p), "l"(pol));
    return v;
}
static __device__ __forceinline__ void stg_cs_f128(float4* p, float4 v) {
    asm volatile("st.global.cs.v4.f32 [%0], {%1,%2,%3,%4};"
                 :: "l"(p), "f"(v.x), "f"(v.y), "f"(v.z), "f"(v.w) : "memory");
}
static __device__ __forceinline__ void stg_cs_f32(float* p, float v) {
    asm volatile("st.global.cs.f32 [%0], %1;" :: "l"(p), "f"(v) : "memory");
}

// One 128-thread block per token.
//  pre : 75 float4 vector copy + 32 float4 bias (evict_last reads, .cs stores)
//  oov : gather spread over ALL 128 threads — each thread does exactly ONE
//        diverged W load (row tid, column c) + one coalesced scalar .cs store,
//        so the LSU burst is split across 4 warps instead of packed in warp 0.
__global__ __launch_bounds__(128) void encoder_kernel(
    const int*    __restrict__ tokens,    // [N_TOKENS]
    const float4* __restrict__ vectors4,  // [N_PRE * 75]
    const float*  __restrict__ W,         // [HIDDEN, IN_SIZE]
    const float*  __restrict__ b,         // [HIDDEN]
    float4*       __restrict__ out4)      // [N_TOKENS * 107]
{
    const int t   = blockIdx.x;
    const int tid = threadIdx.x;
    const int tok = __ldg(&tokens[t]);        // tiny, broadcast

    float4* orow = out4 + (size_t)t * (OUT_DIM / 4);

    if (tok < N_PRE) {
        const uint64_t pol = mk_policy_evict_last();
        const float4* vrow = vectors4 + (size_t)tok * (VEC_DIM / 4);
        if (tid < 75) {
            float4 v = ldg_el_f128(&vrow[tid], pol);
            stg_cs_f128(&orow[tid], v);
        }
        if (tid < 32) {
            const float4* b4 = reinterpret_cast<const float4*>(b);
            stg_cs_f128(&orow[75 + tid], __ldg(&b4[tid]));
        }
    } else {
        const uint64_t pol = mk_policy_evict_last();
        const int c = tok - N_PRE;
        // one diverged gather per thread, issued before the zero stores
        float w  = ldg_el_f32(W + c + (size_t)tid * IN_SIZE, pol);
        float bv = __ldg(&b[tid]);

        const float4 z = make_float4(0.f, 0.f, 0.f, 0.f);
        if (tid < 75) stg_cs_f128(&orow[tid], z);

        float* orow_s = reinterpret_cast<float*>(orow);
        stg_cs_f32(&orow_s[VEC_DIM + tid], bv + w);   // 128 lanes -> 512B coalesced
    }
}

extern "C" void kernel_launch(void* const* d_in, const int* in_sizes, int n_in,
                              void* d_out, int out_size)
{
    // metadata order: tokens (int32), vectors (f32), W (f32), b (f32)
    const int*    tokens  = (const int*)   d_in[0];
    const float4* vectors = (const float4*)d_in[1];
    const float*  W       = (const float*) d_in[2];
    const float*  b       = (const float*) d_in[3];
    float4*       out     = (float4*)      d_out;

    encoder_kernel<<<N_TOKENS, 128>>>(tokens, vectors, W, b, out);
}

// round 13
// speedup vs baseline: 1.0233x; 1.0233x over previous
#include <cuda_runtime.h>
#include <cstdint>

#define N_PRE    50000
#define VEC_DIM  300        // 75 float4
#define HIDDEN   128        // 32 float4
#define IN_SIZE  50000
#define OUT_DIM  428        // 107 float4
#define N_TOKENS (64 * 200)

static __device__ __forceinline__ uint64_t mk_policy_evict_last() {
    uint64_t pol;
    asm volatile("createpolicy.fractional.L2::evict_last.b64 %0, 1.0;"
                 : "=l"(pol));
    return pol;
}
static __device__ __forceinline__ float ldg_el_f32(const float* p, uint64_t pol) {
    float v;
    asm volatile("ld.global.nc.L2::cache_hint.f32 %0, [%1], %2;"
                 : "=f"(v) : "l"(p), "l"(pol));
    return v;
}
static __device__ __forceinline__ float4 ldg_el_f128(const float4* p, uint64_t pol) {
    float4 v;
    asm volatile("ld.global.nc.L2::cache_hint.v4.f32 {%0,%1,%2,%3}, [%4], %5;"
                 : "=f"(v.x), "=f"(v.y), "=f"(v.z), "=f"(v.w)
                 : "l"(p), "l"(pol));
    return v;
}
static __device__ __forceinline__ void stg_cs_f128(float4* p, float4 v) {
    asm volatile("st.global.cs.v4.f32 [%0], {%1,%2,%3,%4};"
                 :: "l"(p), "f"(v.x), "f"(v.y), "f"(v.z), "f"(v.w) : "memory");
}

// One 128-thread block per token, disjoint warp roles:
//  pre : tids 0..74  (warps 0-2) copy the vector row (evict_last -> .cs)
//        tids 96..127 (warp 3)   store the 32 bias float4
//  oov : warp 0 (tids 0..31)     ONLY the gather: 4 independent diverged
//                                evict_last W loads -> b+W -> one float4 .cs
//        tids 32..106 (warps 1-3) the 75 zero float4 stores
__global__ __launch_bounds__(128) void encoder_kernel(
    const int*    __restrict__ tokens,    // [N_TOKENS]
    const float4* __restrict__ vectors4,  // [N_PRE * 75]
    const float*  __restrict__ W,         // [HIDDEN, IN_SIZE]
    const float4* __restrict__ b4,        // [32]
    float4*       __restrict__ out4)      // [N_TOKENS * 107]
{
    const int t   = blockIdx.x;
    const int tid = threadIdx.x;
    const int tok = __ldg(&tokens[t]);        // tiny, broadcast

    float4* orow = out4 + (size_t)t * (OUT_DIM / 4);

    if (tok < N_PRE) {
        if (tid < 75) {
            const uint64_t pol = mk_policy_evict_last();
            const float4* vrow = vectors4 + (size_t)tok * (VEC_DIM / 4);
            float4 v = ldg_el_f128(&vrow[tid], pol);
            stg_cs_f128(&orow[tid], v);
        } else if (tid >= 96) {
            const int j = tid - 96;               // 0..31
            stg_cs_f128(&orow[75 + j], __ldg(&b4[j]));
        }
    } else {
        const int c = tok - N_PRE;
        if (tid < 32) {
            // warp 0: pure gather path, issues immediately
            const uint64_t pol = mk_policy_evict_last();
            const float* Wc = W + c + (size_t)(4 * tid) * IN_SIZE;
            float w0 = ldg_el_f32(Wc, pol);
            float w1 = ldg_el_f32(Wc + (size_t)IN_SIZE, pol);
            float w2 = ldg_el_f32(Wc + (size_t)2 * IN_SIZE, pol);
            float w3 = ldg_el_f32(Wc + (size_t)3 * IN_SIZE, pol);
            float4 bb = __ldg(&b4[tid]);
            float4 h = make_float4(bb.x + w0, bb.y + w1, bb.z + w2, bb.w + w3);
            stg_cs_f128(&orow[75 + tid], h);
        } else if (tid < 107) {
            // warps 1-3: the 75 zero stores (tids 32..106 -> units 0..74)
            const float4 z = make_float4(0.f, 0.f, 0.f, 0.f);
            stg_cs_f128(&orow[tid - 32], z);
        }
    }
}

extern "C" void kernel_launch(void* const* d_in, const int* in_sizes, int n_in,
                              void* d_out, int out_size)
{
    // metadata order: tokens (int32), vectors (f32), W (f32), b (f32)
    const int*    tokens  = (const int*)   d_in[0];
    const float4* vectors = (const float4*)d_in[1];
    const float*  W       = (const float*) d_in[2];
    const float4* b       = (const float4*)d_in[3];
    float4*       out     = (float4*)      d_out;

    encoder_kernel<<<N_TOKENS, 128>>>(tokens, vectors, W, b, out);
}